// round 1
// baseline (speedup 1.0000x reference)
#include <cuda_runtime.h>
#include <math.h>

#define DEVI __device__ __forceinline__

constexpr int LOGN   = 19;
constexpr int FFT_N  = 1 << LOGN;        // 524288
constexpr int M0     = FFT_N / 4;        // 131072 (constant load stride: s*m = N/4 every pass)
constexpr int LX     = 960000;
constexpr int BATCH  = 16;
constexpr int KLEN   = 144000;
constexpr int VALID  = FFT_N - KLEN + 1; // 380289
constexpr int NFRAME = 3;                // ceil(960000 / 380289)
constexpr int NPAIR  = BATCH / 2;        // 8  (two real batches packed per complex signal)
constexpr int NSIG   = NPAIR * NFRAME;   // 24
constexpr int THREADS = 256;

// Ping-pong scratch (~201 MB) + H spectrum scratch (8 MB). Static device arrays:
// allocation-free and graph-capture safe.
__device__ float2 g_A[(size_t)NSIG * FFT_N];
__device__ float2 g_B[(size_t)NSIG * FFT_N];
__device__ float2 g_hA[FFT_N];
__device__ float2 g_hB[FFT_N];

DEVI float2* mainbuf(int i) { return i ? g_B : g_A; }
DEVI float2* hbuf(int i)    { return i ? g_hB : g_hA; }

DEVI float2 cadd(float2 a, float2 b) { return make_float2(a.x + b.x, a.y + b.y); }
DEVI float2 csub(float2 a, float2 b) { return make_float2(a.x - b.x, a.y - b.y); }
DEVI float2 cmul(float2 a, float2 b) {
    return make_float2(a.x * b.x - a.y * b.y, a.x * b.y + a.y * b.x);
}

// Stockham DIF radix-4 butterfly. SIGN = -1 forward, +1 inverse.
// Twiddle w = exp(SIGN * 2*pi*i * p / n); angle magnitude < pi/2 (p < n/4).
template<int SIGN>
DEVI void bfly4(const float2 v[4], int p, int n, float2 o[4]) {
    float2 apc = cadd(v[0], v[2]);
    float2 amc = csub(v[0], v[2]);
    float2 bpd = cadd(v[1], v[3]);
    float2 bmd = csub(v[1], v[3]);
    float2 jb  = make_float2(-(float)SIGN * bmd.y, (float)SIGN * bmd.x); // SIGN*i*bmd
    float ang = (float)SIGN * 6.283185307179586f * ((float)p / (float)n);
    float sw, cw;
    sincosf(ang, &sw, &cw);
    float2 w1 = make_float2(cw, sw);
    float2 w2 = cmul(w1, w1);
    float2 w3 = cmul(w2, w1);
    o[0] = cadd(apc, bpd);
    o[1] = cmul(w1, cadd(amc, jb));
    o[2] = cmul(w2, csub(apc, bpd));
    o[3] = cmul(w3, csub(amc, jb));
}

// ---------------- Forward pass 0: frame gather (zero-pad + pack 2 batches) ----------------
// Signal sig = pair*NFRAME + f packs batches (2*pair, 2*pair+1), frame f.
// Segment start in x: f*VALID - (K-1)  (overlap-save).
__global__ void fwd_pass0_gather(const float* __restrict__ x) {
    int tid = blockIdx.x * blockDim.x + threadIdx.x;
    if (tid >= NSIG * M0) return;
    int sig  = tid / M0;
    int p    = tid - sig * M0;
    int pair = sig / NFRAME;
    int f    = sig - pair * NFRAME;
    const float* x0 = x + (size_t)(2 * pair) * LX;
    const float* x1 = x0 + LX;
    long base = (long)f * VALID - (KLEN - 1);
    float2 v[4];
#pragma unroll
    for (int t = 0; t < 4; t++) {
        long pos = base + p + (long)t * M0;
        float re = 0.f, im = 0.f;
        if (pos >= 0 && pos < LX) { re = x0[pos]; im = x1[pos]; }
        v[t] = make_float2(re, im);
    }
    float2 o[4];
    bfly4<-1>(v, p, FFT_N, o);
    float2* xo = g_A + (size_t)sig * FFT_N + 4 * (size_t)p;
#pragma unroll
    for (int t = 0; t < 4; t++) xo[t] = o[t];
}

// ---------------- H pass 0: build h (time-reversed tanh taps, h[0]=1), pre-scale 1/N ----------------
__global__ void h_pass0_gather(const float* __restrict__ irp) {
    int p = blockIdx.x * blockDim.x + threadIdx.x;
    if (p >= M0) return;
    const float invN = 1.0f / (float)FFT_N;
    float2 v[4];
#pragma unroll
    for (int t = 0; t < 4; t++) {
        int idx = p + t * M0;
        float hv = 0.f;
        if (idx == 0)          hv = 1.0f;
        else if (idx < KLEN)   hv = tanhf(irp[KLEN - 1 - idx]);
        v[t] = make_float2(hv * invN, 0.f);
    }
    float2 o[4];
    bfly4<-1>(v, p, FFT_N, o);
    float2* xo = g_hA + 4 * (size_t)p;
#pragma unroll
    for (int t = 0; t < 4; t++) xo[t] = o[t];
}

// ---------------- Generic Stockham radix-4 pass (pass i: log2s = 2i, n = N>>log2s) ----------------
template<int SIGN>
__global__ void r4_pass(int useH, int inb, int log2s, int nsig) {
    int tid = blockIdx.x * blockDim.x + threadIdx.x;
    if (tid >= nsig * M0) return;
    int sig = tid / M0;
    int r   = tid - sig * M0;
    int s = 1 << log2s;
    int q = r & (s - 1);
    int p = r >> log2s;
    int n = FFT_N >> log2s;
    const float2* xi = (useH ? hbuf(inb)     : mainbuf(inb))     + (size_t)sig * FFT_N;
    float2*       xo = (useH ? hbuf(inb ^ 1) : mainbuf(inb ^ 1)) + (size_t)sig * FFT_N;
    int ibase = q + s * p;   // loads at ibase + t*N/4 (s*m == N/4 for every pass)
    float2 v[4];
#pragma unroll
    for (int t = 0; t < 4; t++) v[t] = xi[ibase + t * M0];
    float2 o[4];
    bfly4<SIGN>(v, p, n, o);
    int ob = q + 4 * s * p;  // stores at ob + t*s
#pragma unroll
    for (int t = 0; t < 4; t++) xo[ob + t * s] = o[t];
}

// ---------------- Final radix-2 pass (n=2, s=N/2, twiddle = 1, sign-independent) ----------------
__global__ void r2_pass(int useH, int inb, int nsig) {
    const int per = FFT_N / 2;
    int tid = blockIdx.x * blockDim.x + threadIdx.x;
    if (tid >= nsig * per) return;
    int sig = tid / per;
    int q   = tid - sig * per;
    const float2* xi = (useH ? hbuf(inb)     : mainbuf(inb))     + (size_t)sig * FFT_N;
    float2*       xo = (useH ? hbuf(inb ^ 1) : mainbuf(inb ^ 1)) + (size_t)sig * FFT_N;
    float2 a = xi[q], b = xi[q + per];
    xo[q]       = cadd(a, b);
    xo[q + per] = csub(a, b);
}

// ---------------- Inverse pass 0 fused with pointwise multiply by Hfft (already /N) ----------------
__global__ void inv_pass0_mulH() {
    int tid = blockIdx.x * blockDim.x + threadIdx.x;
    if (tid >= NSIG * M0) return;
    int sig = tid / M0;
    int p   = tid - sig * M0;
    const float2* xi = g_B + (size_t)sig * FFT_N;
    float2 v[4];
#pragma unroll
    for (int t = 0; t < 4; t++) {
        int idx = p + t * M0;
        v[t] = cmul(xi[idx], g_hB[idx]);
    }
    float2 o[4];
    bfly4<1>(v, p, FFT_N, o);
    float2* xo = g_A + (size_t)sig * FFT_N + 4 * (size_t)p;
#pragma unroll
    for (int t = 0; t < 4; t++) xo[t] = o[t];
}

// ---------------- Inverse final radix-2 fused with valid-region scatter to d_out ----------------
DEVI void scatter_store(float* __restrict__ dout, int b0, int f, int idx, float2 v) {
    int t = idx - (KLEN - 1);            // valid samples start at K-1 (no circular wrap)
    if (t < 0) return;                   // t < VALID always holds (idx < N)
    long nout = (long)f * VALID + t;
    if (nout >= LX) return;
    dout[(size_t)b0 * LX + nout]       = v.x;  // real part -> batch b0
    dout[(size_t)(b0 + 1) * LX + nout] = v.y;  // imag part -> batch b0+1
}

__global__ void inv_r2_scatter(float* __restrict__ dout) {
    const int per = FFT_N / 2;
    int tid = blockIdx.x * blockDim.x + threadIdx.x;
    if (tid >= NSIG * per) return;
    int sig = tid / per;
    int q   = tid - sig * per;
    int pair = sig / NFRAME;
    int f    = sig - pair * NFRAME;
    const float2* xi = g_A + (size_t)sig * FFT_N;
    float2 a = xi[q], b = xi[q + per];
    scatter_store(dout, 2 * pair, f, q,       cadd(a, b));
    scatter_store(dout, 2 * pair, f, q + per, csub(a, b));
}

extern "C" void kernel_launch(void* const* d_in, const int* in_sizes, int n_in,
                              void* d_out, int out_size) {
    (void)in_sizes; (void)n_in; (void)out_size;
    const float* x   = (const float*)d_in[0];
    const float* irp = (const float*)d_in[1];
    float* out = (float*)d_out;

    const int mainR4 = (NSIG * M0 + THREADS - 1) / THREADS;            // 12288
    const int mainR2 = (NSIG * (FFT_N / 2) + THREADS - 1) / THREADS;   // 24576
    const int hR4    = (M0 + THREADS - 1) / THREADS;                   // 512
    const int hR2    = ((FFT_N / 2) + THREADS - 1) / THREADS;          // 1024

    // --- H spectrum (recomputed each launch; deterministic) -> ends in g_hB ---
    h_pass0_gather<<<hR4, THREADS>>>(irp);
    for (int i = 1; i <= 8; i++)
        r4_pass<-1><<<hR4, THREADS>>>(1, (i & 1) ? 0 : 1, 2 * i, 1);
    r2_pass<<<hR2, THREADS>>>(1, 0, 1);

    // --- Forward FFT of 24 packed frames: gather -> A, ping-pong, spectrum ends in g_B ---
    fwd_pass0_gather<<<mainR4, THREADS>>>(x);
    for (int i = 1; i <= 8; i++)
        r4_pass<-1><<<mainR4, THREADS>>>(0, (i & 1) ? 0 : 1, 2 * i, NSIG);
    r2_pass<<<mainR2, THREADS>>>(0, 0, NSIG);

    // --- Pointwise *Hfft fused into inverse pass 0; inverse FFT; scatter to d_out ---
    inv_pass0_mulH<<<mainR4, THREADS>>>();
    for (int i = 1; i <= 8; i++)
        r4_pass<1><<<mainR4, THREADS>>>(0, (i & 1) ? 0 : 1, 2 * i, NSIG);
    inv_r2_scatter<<<mainR2, THREADS>>>(out);
}

// round 2
// speedup vs baseline: 2.3601x; 2.3601x over previous
#include <cuda_runtime.h>
#include <math.h>

#define DEVI __device__ __forceinline__

constexpr int LOGN   = 19;
constexpr int FFT_N  = 1 << LOGN;        // 524288 = 512 x 1024
constexpr int N1     = 512;              // column FFT length (passes A, C)
constexpr int N2     = 1024;             // row FFT length (pass B)
constexpr int LX     = 960000;
constexpr int KLEN   = 144000;
constexpr int VALID  = FFT_N - KLEN + 1; // 380289
constexpr int NFRAME = 3;
constexpr int NPAIR  = 8;                // 16 batches packed as 8 complex signals
constexpr int NSIG   = NPAIR * NFRAME;   // 24
constexpr float INV_N = 1.0f / (float)FFT_N;
constexpr float TWO_PI = 6.2831853071795865f;

// Static device scratch: ping (g_A), pong (g_B), H time (g_hT), H spectrum (g_hS).
__device__ float2 g_A[(size_t)NSIG * FFT_N];
__device__ float2 g_B[(size_t)NSIG * FFT_N];
__device__ float2 g_hT[FFT_N];
__device__ float2 g_hS[FFT_N];

DEVI float2 cadd(float2 a, float2 b) { return make_float2(a.x + b.x, a.y + b.y); }
DEVI float2 csub(float2 a, float2 b) { return make_float2(a.x - b.x, a.y - b.y); }
DEVI float2 cmul(float2 a, float2 b) {
    return make_float2(a.x * b.x - a.y * b.y, a.x * b.y + a.y * b.x);
}

// Stockham DIF radix-4 butterfly, pf = p/n. SIGN=-1 fwd, +1 inv.
template<int SIGN>
DEVI void bfly4(const float2 v[4], float pf, float2 o[4]) {
    float2 apc = cadd(v[0], v[2]);
    float2 amc = csub(v[0], v[2]);
    float2 bpd = cadd(v[1], v[3]);
    float2 bmd = csub(v[1], v[3]);
    float2 jb  = make_float2(-(float)SIGN * bmd.y, (float)SIGN * bmd.x);
    float sn, cs;
    __sincosf((float)SIGN * TWO_PI * pf, &sn, &cs);
    float2 w1 = make_float2(cs, sn);
    float2 w2 = cmul(w1, w1);
    float2 w3 = cmul(w2, w1);
    o[0] = cadd(apc, bpd);
    o[1] = cmul(w1, cadd(amc, jb));
    o[2] = cmul(w2, csub(apc, bpd));
    o[3] = cmul(w3, csub(amc, jb));
}

// p == 0 butterfly (no twiddles).
template<int SIGN>
DEVI void bfly4_nt(const float2 v[4], float2 o[4]) {
    float2 apc = cadd(v[0], v[2]);
    float2 amc = csub(v[0], v[2]);
    float2 bpd = cadd(v[1], v[3]);
    float2 bmd = csub(v[1], v[3]);
    float2 jb  = make_float2(-(float)SIGN * bmd.y, (float)SIGN * bmd.x);
    o[0] = cadd(apc, bpd);
    o[1] = cadd(amc, jb);
    o[2] = csub(apc, bpd);
    o[3] = csub(amc, jb);
}

// 8 independent FFT-512 in shared memory, pitch-9 layout sb[row*9 + col].
// 512 threads; Stockham self-sorting (natural in / natural out).
template<int SIGN>
DEVI void fft512x8(float2* sb) {
    int tid = threadIdx.x;
#pragma unroll
    for (int st = 0; st < 4; st++) {
        int s = 1 << (2 * st);
        float invn = 1.0f / (float)(512 >> (2 * st));
        float2 v[2][4], o[2][4];
#pragma unroll
        for (int j = 0; j < 2; j++) {
            int w = tid + 512 * j;
            int c = w & 7, rr = w >> 3;     // q + s*p == rr
#pragma unroll
            for (int t = 0; t < 4; t++) v[j][t] = sb[(rr + 128 * t) * 9 + c];
            int p = rr >> (2 * st);
            bfly4<SIGN>(v[j], (float)p * invn, o[j]);
        }
        __syncthreads();
#pragma unroll
        for (int j = 0; j < 2; j++) {
            int w = tid + 512 * j;
            int c = w & 7, rr = w >> 3;
            int q = rr & (s - 1), p = rr >> (2 * st);
            int ob = q + 4 * s * p;
#pragma unroll
            for (int t = 0; t < 4; t++) sb[(ob + t * s) * 9 + c] = o[j][t];
        }
        __syncthreads();
    }
    // final radix-2 (s=256, twiddle-free)
    float2 a[4], b[4];
#pragma unroll
    for (int j = 0; j < 4; j++) {
        int w = tid + 512 * j;
        int c = w & 7, qq = w >> 3;
        a[j] = sb[qq * 9 + c];
        b[j] = sb[(qq + 256) * 9 + c];
    }
    __syncthreads();
#pragma unroll
    for (int j = 0; j < 4; j++) {
        int w = tid + 512 * j;
        int c = w & 7, qq = w >> 3;
        sb[qq * 9 + c]         = cadd(a[j], b[j]);
        sb[(qq + 256) * 9 + c] = csub(a[j], b[j]);
    }
    __syncthreads();
}

// ---------------- Pass A (main): gather + column FFT-512 + twiddle W_N^{n2*k1} ----------------
__global__ void __launch_bounds__(512) passA_main(const float* __restrict__ x) {
    __shared__ __align__(16) float2 sb[512 * 9];
    int sig = blockIdx.x >> 7;
    int cb  = (blockIdx.x & 127) << 3;
    int pair = sig / NFRAME;
    int f    = sig - pair * NFRAME;
    const float* x0 = x + (size_t)(2 * pair) * LX;
    const float* x1 = x0 + LX;
    long base = (long)f * VALID - (KLEN - 1);

#pragma unroll
    for (int e = 0; e < 8; e++) {
        int u = threadIdx.x + 512 * e;
        int n1 = u >> 3, c = u & 7, n2 = cb + c;
        long pos = base + (long)n1 * N2 + n2;
        float re = 0.f, im = 0.f;
        if (pos >= 0 && pos < LX) { re = x0[pos]; im = x1[pos]; }
        sb[n1 * 9 + c] = make_float2(re, im);
    }
    __syncthreads();
    fft512x8<-1>(sb);

    float2* out = g_A + (size_t)sig * FFT_N;
#pragma unroll
    for (int e = 0; e < 8; e++) {
        int u = threadIdx.x + 512 * e;
        int k1 = u >> 3, c = u & 7, n2 = cb + c;
        float2 val = sb[k1 * 9 + c];
        float fr = (float)(n2 * k1) * INV_N;   // exact: product < 2^19
        fr -= rintf(fr);                       // reduce to [-0.5, 0.5]
        float sn, cs;
        __sincosf(-TWO_PI * fr, &sn, &cs);
        out[(size_t)k1 * N2 + n2] = cmul(val, make_float2(cs, sn));
    }
}

// ---------------- Pass A (H): build h (reversed tanh taps, h[0]=1, pre /N), col FFT, twiddle ----
__global__ void __launch_bounds__(512) passA_H(const float* __restrict__ irp) {
    __shared__ __align__(16) float2 sb[512 * 9];
    int cb = blockIdx.x << 3;
#pragma unroll
    for (int e = 0; e < 8; e++) {
        int u = threadIdx.x + 512 * e;
        int n1 = u >> 3, c = u & 7, n2 = cb + c;
        int n = n1 * N2 + n2;
        float hv = 0.f;
        if (n == 0)         hv = 1.0f;
        else if (n < KLEN)  hv = tanhf(irp[KLEN - 1 - n]);
        sb[n1 * 9 + c] = make_float2(hv * INV_N, 0.f);
    }
    __syncthreads();
    fft512x8<-1>(sb);
#pragma unroll
    for (int e = 0; e < 8; e++) {
        int u = threadIdx.x + 512 * e;
        int k1 = u >> 3, c = u & 7, n2 = cb + c;
        float2 val = sb[k1 * 9 + c];
        float fr = (float)(n2 * k1) * INV_N;
        fr -= rintf(fr);
        float sn, cs;
        __sincosf(-TWO_PI * fr, &sn, &cs);
        g_hT[(size_t)k1 * N2 + n2] = cmul(val, make_float2(cs, sn));
    }
}

// ---------------- Pass B (H): forward row FFT-1024 only ----------------
__global__ void __launch_bounds__(256) passB_H() {
    __shared__ __align__(16) float2 sb[1024];
    int k1 = blockIdx.x;
    const float2* rin = g_hT + (size_t)k1 * N2;
    int tid = threadIdx.x;
    float2 v[4], o[4];
#pragma unroll
    for (int t = 0; t < 4; t++) v[t] = rin[tid + 256 * t];
    bfly4<-1>(v, (float)tid * (1.0f / 1024.f), o);
    float4* s4 = (float4*)sb;
    s4[2 * tid]     = make_float4(o[0].x, o[0].y, o[1].x, o[1].y);
    s4[2 * tid + 1] = make_float4(o[2].x, o[2].y, o[3].x, o[3].y);
    __syncthreads();
    int g = tid >> 2;
#pragma unroll
    for (int st = 1; st < 4; st++) {
        int s = 1 << (2 * st);
        float invn = 1.0f / (float)(1024 >> (2 * st));
        int q = tid & (s - 1), p = tid >> (2 * st);
#pragma unroll
        for (int t = 0; t < 4; t++) v[t] = sb[tid + 256 * t];
        bfly4<-1>(v, (float)p * invn, o);
        __syncthreads();
        int ob = q + 4 * s * p;
#pragma unroll
        for (int tt = 0; tt < 4; tt++) { int t = (tt + g) & 3; sb[ob + t * s] = o[t]; }
        __syncthreads();
    }
#pragma unroll
    for (int t = 0; t < 4; t++) v[t] = sb[tid + 256 * t];
    bfly4_nt<-1>(v, o);   // s=256 stage: p==0
#pragma unroll
    for (int t = 0; t < 4; t++) g_hS[(size_t)k1 * N2 + tid + 256 * t] = o[t];
}

// ---------------- Pass B (main): row FFT-1024, xH (regs), row iFFT-1024, inv twiddle ----------
__global__ void __launch_bounds__(256) passB_main() {
    __shared__ __align__(16) float2 sb[1024];
    int sig = blockIdx.x >> 9;
    int k1  = blockIdx.x & 511;
    const float2* rin  = g_A + (size_t)sig * FFT_N + (size_t)k1 * N2;
    const float2* hrow = g_hS + (size_t)k1 * N2;
    float2*       rout = g_B + (size_t)sig * FFT_N + (size_t)k1 * N2;
    int tid = threadIdx.x;
    int g = tid >> 2;
    float2 v[4], o[4];
    float4* s4 = (float4*)sb;

    // ---- forward FFT-1024 ----
#pragma unroll
    for (int t = 0; t < 4; t++) v[t] = rin[tid + 256 * t];
    bfly4<-1>(v, (float)tid * (1.0f / 1024.f), o);
    s4[2 * tid]     = make_float4(o[0].x, o[0].y, o[1].x, o[1].y);
    s4[2 * tid + 1] = make_float4(o[2].x, o[2].y, o[3].x, o[3].y);
    __syncthreads();
#pragma unroll
    for (int st = 1; st < 4; st++) {
        int s = 1 << (2 * st);
        float invn = 1.0f / (float)(1024 >> (2 * st));
        int q = tid & (s - 1), p = tid >> (2 * st);
#pragma unroll
        for (int t = 0; t < 4; t++) v[t] = sb[tid + 256 * t];
        bfly4<-1>(v, (float)p * invn, o);
        __syncthreads();
        int ob = q + 4 * s * p;
#pragma unroll
        for (int tt = 0; tt < 4; tt++) { int t = (tt + g) & 3; sb[ob + t * s] = o[t]; }
        __syncthreads();
    }
#pragma unroll
    for (int t = 0; t < 4; t++) v[t] = sb[tid + 256 * t];
    bfly4_nt<-1>(v, o);           // fwd last stage -> spectrum at tid+256t (registers)

    // ---- pointwise multiply by H in registers ----
#pragma unroll
    for (int t = 0; t < 4; t++) o[t] = cmul(o[t], hrow[tid + 256 * t]);

    // ---- inverse FFT-1024 (stage 0 input == register layout) ----
    bfly4<1>(o, (float)tid * (1.0f / 1024.f), v);
    __syncthreads();              // protect fwd-last loads from inv stores
    s4[2 * tid]     = make_float4(v[0].x, v[0].y, v[1].x, v[1].y);
    s4[2 * tid + 1] = make_float4(v[2].x, v[2].y, v[3].x, v[3].y);
    __syncthreads();
#pragma unroll
    for (int st = 1; st < 4; st++) {
        int s = 1 << (2 * st);
        float invn = 1.0f / (float)(1024 >> (2 * st));
        int q = tid & (s - 1), p = tid >> (2 * st);
#pragma unroll
        for (int t = 0; t < 4; t++) v[t] = sb[tid + 256 * t];
        bfly4<1>(v, (float)p * invn, o);
        __syncthreads();
        int ob = q + 4 * s * p;
#pragma unroll
        for (int tt = 0; tt < 4; tt++) { int t = (tt + g) & 3; sb[ob + t * s] = o[t]; }
        __syncthreads();
    }
#pragma unroll
    for (int t = 0; t < 4; t++) v[t] = sb[tid + 256 * t];
    bfly4_nt<1>(v, o);            // inv last stage -> time index n2 = tid+256t

    // ---- inverse cross twiddle W_N^{-n2*k1} + contiguous store ----
#pragma unroll
    for (int t = 0; t < 4; t++) {
        int n2 = tid + 256 * t;
        float fr = (float)(n2 * k1) * INV_N;
        fr -= rintf(fr);
        float sn, cs;
        __sincosf(TWO_PI * fr, &sn, &cs);
        rout[n2] = cmul(o[t], make_float2(cs, sn));
    }
}

// ---------------- Pass C: column iFFT-512 + overlap-save scatter ----------------
__global__ void __launch_bounds__(512) passC(float* __restrict__ dout) {
    __shared__ __align__(16) float2 sb[512 * 9];
    int sig = blockIdx.x >> 7;
    int cb  = (blockIdx.x & 127) << 3;
    int pair = sig / NFRAME;
    int f    = sig - pair * NFRAME;
    const float2* in = g_B + (size_t)sig * FFT_N;

#pragma unroll
    for (int e = 0; e < 8; e++) {
        int u = threadIdx.x + 512 * e;
        int k1 = u >> 3, c = u & 7;
        sb[k1 * 9 + c] = in[(size_t)k1 * N2 + cb + c];
    }
    __syncthreads();
    fft512x8<1>(sb);

    int b0 = 2 * pair;
#pragma unroll
    for (int e = 0; e < 8; e++) {
        int u = threadIdx.x + 512 * e;
        int n1 = u >> 3, c = u & 7, n2 = cb + c;
        int n = n1 * N2 + n2;
        int t = n - (KLEN - 1);          // valid region; t < VALID always
        if (t >= 0) {
            long no = (long)f * VALID + t;
            if (no < LX) {
                float2 vv = sb[n1 * 9 + c];
                dout[(size_t)b0 * LX + no]       = vv.x;
                dout[((size_t)b0 + 1) * LX + no] = vv.y;
            }
        }
    }
}

extern "C" void kernel_launch(void* const* d_in, const int* in_sizes, int n_in,
                              void* d_out, int out_size) {
    (void)in_sizes; (void)n_in; (void)out_size;
    const float* x   = (const float*)d_in[0];
    const float* irp = (const float*)d_in[1];
    float* out = (float*)d_out;

    passA_H<<<N2 / 8, 512>>>(irp);           // 128 blocks
    passB_H<<<N1, 256>>>();                  // 512 blocks
    passA_main<<<NSIG * (N2 / 8), 512>>>(x); // 3072 blocks
    passB_main<<<NSIG * N1, 256>>>();        // 12288 blocks
    passC<<<NSIG * (N2 / 8), 512>>>(out);    // 3072 blocks
}

// round 3
// speedup vs baseline: 3.6678x; 1.5541x over previous
#include <cuda_runtime.h>
#include <math.h>

#define DEVI __device__ __forceinline__

constexpr int FFT_N  = 1 << 19;          // 524288 = 512 x 1024
constexpr int N1     = 512;              // column FFT length (passes A, C)
constexpr int N2     = 1024;             // row FFT length (pass B)
constexpr int LX     = 960000;
constexpr int KLEN   = 144000;
constexpr int VALID  = FFT_N - KLEN + 1; // 380289
constexpr int NFRAME = 3;
constexpr int NPAIR  = 8;                // 16 batches packed as 8 complex signals
constexpr int NSIG   = NPAIR * NFRAME;   // 24
constexpr float INV_N = 1.0f / (float)FFT_N;
constexpr float TWO_PI = 6.2831853071795865f;

// Static device scratch (allocation-free, graph-safe).
__device__ float2 g_A[(size_t)NSIG * FFT_N];
__device__ float2 g_B[(size_t)NSIG * FFT_N];
__device__ float2 g_hT[FFT_N];
__device__ float2 g_hS[FFT_N];
__device__ float2 g_W1024[1024];   // e^{-2*pi*i*k/1024}
__device__ float2 g_W512[512];     // e^{-2*pi*i*k/512}

DEVI float2 cadd(float2 a, float2 b) { return make_float2(a.x + b.x, a.y + b.y); }
DEVI float2 csub(float2 a, float2 b) { return make_float2(a.x - b.x, a.y - b.y); }
DEVI float2 cmul(float2 a, float2 b) {
    return make_float2(a.x * b.x - a.y * b.y, a.x * b.y + a.y * b.x);
}

// LUT twiddle fetch; table stores forward (SIGN=-1) values, conj for inverse.
template<int SIGN>
DEVI float2 twl(const float2* T, int k) {
    float2 w = __ldg(T + k);
    if (SIGN > 0) w.y = -w.y;
    return w;
}

// ---------------- 8-point DFT in registers, natural in/out ----------------
// X[k] = sum_m v[m] * e^{SIGN*2*pi*i*k*m/8}
template<int SIGN>
DEVI void fft8(float2 v[8]) {
    const float C1 = 0.70710678118654752f;
    const float S = (float)SIGN;
    float2 y0 = cadd(v[0], v[4]), z0 = csub(v[0], v[4]);
    float2 y1 = cadd(v[1], v[5]), z1 = csub(v[1], v[5]);
    float2 y2 = cadd(v[2], v[6]), z2 = csub(v[2], v[6]);
    float2 y3 = cadd(v[3], v[7]), z3 = csub(v[3], v[7]);
    z1 = make_float2(C1 * (z1.x - S * z1.y), C1 * (S * z1.x + z1.y));   // * e^{S i pi/4}
    z2 = make_float2(-S * z2.y, S * z2.x);                              // * S*i
    z3 = make_float2(-C1 * (z3.x + S * z3.y), C1 * (S * z3.x - z3.y));  // * e^{S 3i pi/4}
    {
        float2 t0 = cadd(y0, y2), t1 = csub(y0, y2);
        float2 t2 = cadd(y1, y3), t3 = csub(y1, y3);
        float2 it3 = make_float2(-S * t3.y, S * t3.x);
        v[0] = cadd(t0, t2); v[2] = cadd(t1, it3);
        v[4] = csub(t0, t2); v[6] = csub(t1, it3);
    }
    {
        float2 t0 = cadd(z0, z2), t1 = csub(z0, z2);
        float2 t2 = cadd(z1, z3), t3 = csub(z1, z3);
        float2 it3 = make_float2(-S * t3.y, S * t3.x);
        v[1] = cadd(t0, t2); v[3] = cadd(t1, it3);
        v[5] = csub(t0, t2); v[7] = csub(t1, it3);
    }
}

// ---------------- LUT init (tiny, runs first every launch; deterministic) ----------------
__global__ void init_luts() {
    int k = blockIdx.x * 256 + threadIdx.x;
    if (k < 1024) {
        double s, c;
        sincospi(-2.0 * (double)k / 1024.0, &s, &c);
        g_W1024[k] = make_float2((float)c, (float)s);
    }
    if (k < 512) {
        double s, c;
        sincospi(-2.0 * (double)k / 512.0, &s, &c);
        g_W512[k] = make_float2((float)c, (float)s);
    }
}

// ================= legacy radix-4 helpers (H pipeline only; known-correct) =================
template<int SIGN>
DEVI void bfly4(const float2 v[4], float pf, float2 o[4]) {
    float2 apc = cadd(v[0], v[2]);
    float2 amc = csub(v[0], v[2]);
    float2 bpd = cadd(v[1], v[3]);
    float2 bmd = csub(v[1], v[3]);
    float2 jb  = make_float2(-(float)SIGN * bmd.y, (float)SIGN * bmd.x);
    float sn, cs;
    __sincosf((float)SIGN * TWO_PI * pf, &sn, &cs);
    float2 w1 = make_float2(cs, sn);
    float2 w2 = cmul(w1, w1);
    float2 w3 = cmul(w2, w1);
    o[0] = cadd(apc, bpd);
    o[1] = cmul(w1, cadd(amc, jb));
    o[2] = cmul(w2, csub(apc, bpd));
    o[3] = cmul(w3, csub(amc, jb));
}

template<int SIGN>
DEVI void bfly4_nt(const float2 v[4], float2 o[4]) {
    float2 apc = cadd(v[0], v[2]);
    float2 amc = csub(v[0], v[2]);
    float2 bpd = cadd(v[1], v[3]);
    float2 bmd = csub(v[1], v[3]);
    float2 jb  = make_float2(-(float)SIGN * bmd.y, (float)SIGN * bmd.x);
    o[0] = cadd(apc, bpd);
    o[1] = cadd(amc, jb);
    o[2] = csub(apc, bpd);
    o[3] = csub(amc, jb);
}

template<int SIGN>
DEVI void fft512x8(float2* sb) {
    int tid = threadIdx.x;
#pragma unroll
    for (int st = 0; st < 4; st++) {
        int s = 1 << (2 * st);
        float invn = 1.0f / (float)(512 >> (2 * st));
        float2 v[2][4], o[2][4];
#pragma unroll
        for (int j = 0; j < 2; j++) {
            int w = tid + 512 * j;
            int c = w & 7, rr = w >> 3;
#pragma unroll
            for (int t = 0; t < 4; t++) v[j][t] = sb[(rr + 128 * t) * 9 + c];
            int p = rr >> (2 * st);
            bfly4<SIGN>(v[j], (float)p * invn, o[j]);
        }
        __syncthreads();
#pragma unroll
        for (int j = 0; j < 2; j++) {
            int w = tid + 512 * j;
            int c = w & 7, rr = w >> 3;
            int q = rr & (s - 1), p = rr >> (2 * st);
            int ob = q + 4 * s * p;
#pragma unroll
            for (int t = 0; t < 4; t++) sb[(ob + t * s) * 9 + c] = o[j][t];
        }
        __syncthreads();
    }
    float2 a[4], b[4];
#pragma unroll
    for (int j = 0; j < 4; j++) {
        int w = tid + 512 * j;
        int c = w & 7, qq = w >> 3;
        a[j] = sb[qq * 9 + c];
        b[j] = sb[(qq + 256) * 9 + c];
    }
    __syncthreads();
#pragma unroll
    for (int j = 0; j < 4; j++) {
        int w = tid + 512 * j;
        int c = w & 7, qq = w >> 3;
        sb[qq * 9 + c]         = cadd(a[j], b[j]);
        sb[(qq + 256) * 9 + c] = csub(a[j], b[j]);
    }
    __syncthreads();
}

__global__ void __launch_bounds__(512) passA_H(const float* __restrict__ irp) {
    __shared__ __align__(16) float2 sb[512 * 9];
    int cb = blockIdx.x << 3;
#pragma unroll
    for (int e = 0; e < 8; e++) {
        int u = threadIdx.x + 512 * e;
        int n1 = u >> 3, c = u & 7, n2 = cb + c;
        int n = n1 * N2 + n2;
        float hv = 0.f;
        if (n == 0)         hv = 1.0f;
        else if (n < KLEN)  hv = tanhf(irp[KLEN - 1 - n]);
        sb[n1 * 9 + c] = make_float2(hv * INV_N, 0.f);
    }
    __syncthreads();
    fft512x8<-1>(sb);
#pragma unroll
    for (int e = 0; e < 8; e++) {
        int u = threadIdx.x + 512 * e;
        int k1 = u >> 3, c = u & 7, n2 = cb + c;
        float2 val = sb[k1 * 9 + c];
        float fr = (float)(n2 * k1) * INV_N;
        fr -= rintf(fr);
        float sn, cs;
        __sincosf(-TWO_PI * fr, &sn, &cs);
        g_hT[(size_t)k1 * N2 + n2] = cmul(val, make_float2(cs, sn));
    }
}

__global__ void __launch_bounds__(256) passB_H() {
    __shared__ __align__(16) float2 sb[1024];
    int k1 = blockIdx.x;
    const float2* rin = g_hT + (size_t)k1 * N2;
    int tid = threadIdx.x;
    float2 v[4], o[4];
#pragma unroll
    for (int t = 0; t < 4; t++) v[t] = rin[tid + 256 * t];
    bfly4<-1>(v, (float)tid * (1.0f / 1024.f), o);
    float4* s4 = (float4*)sb;
    s4[2 * tid]     = make_float4(o[0].x, o[0].y, o[1].x, o[1].y);
    s4[2 * tid + 1] = make_float4(o[2].x, o[2].y, o[3].x, o[3].y);
    __syncthreads();
    int g = tid >> 2;
#pragma unroll
    for (int st = 1; st < 4; st++) {
        int s = 1 << (2 * st);
        float invn = 1.0f / (float)(1024 >> (2 * st));
        int q = tid & (s - 1), p = tid >> (2 * st);
#pragma unroll
        for (int t = 0; t < 4; t++) v[t] = sb[tid + 256 * t];
        bfly4<-1>(v, (float)p * invn, o);
        __syncthreads();
        int ob = q + 4 * s * p;
#pragma unroll
        for (int tt = 0; tt < 4; tt++) { int t = (tt + g) & 3; sb[ob + t * s] = o[t]; }
        __syncthreads();
    }
#pragma unroll
    for (int t = 0; t < 4; t++) v[t] = sb[tid + 256 * t];
    bfly4_nt<-1>(v, o);
#pragma unroll
    for (int t = 0; t < 4; t++) g_hS[(size_t)k1 * N2 + tid + 256 * t] = o[t];
}

// ================= main passes (radix-8 + LUT) =================

// ---------------- Pass A: gather + column FFT-512 (8.8.8) + cross twiddle ----------------
__global__ void __launch_bounds__(512, 2) passA_main(const float* __restrict__ x) {
    __shared__ __align__(16) float2 sb[512 * 9];
    int sig = blockIdx.x >> 7;
    int cb  = (blockIdx.x & 127) << 3;
    int pair = sig / NFRAME;
    int f    = sig - pair * NFRAME;
    const float* x0 = x + (size_t)(2 * pair) * LX;
    const float* x1 = x0 + LX;
    long base = (long)f * VALID - (KLEN - 1);

    int c = threadIdx.x & 7, r = threadIdx.x >> 3;  // r in [0,64)
    int n2 = cb + c;
    float2 v[8];
#pragma unroll
    for (int j = 0; j < 8; j++) {
        long pos = base + (long)(r + 64 * j) * N2 + n2;
        float re = 0.f, im = 0.f;
        if (pos >= 0 && pos < LX) { re = __ldg(x0 + pos); im = __ldg(x1 + pos); }
        v[j] = make_float2(re, im);
    }
    // stage 0: s=1, n=512, p=r
    fft8<-1>(v);
#pragma unroll
    for (int j = 1; j < 8; j++) v[j] = cmul(v[j], twl<-1>(g_W512, j * r));
#pragma unroll
    for (int j = 0; j < 8; j++) sb[(8 * r + j) * 9 + c] = v[j];
    __syncthreads();
    // stage 1: s=8, n=64
#pragma unroll
    for (int j = 0; j < 8; j++) v[j] = sb[(r + 64 * j) * 9 + c];
    fft8<-1>(v);
    {
        int q = r & 7, p = r >> 3;
#pragma unroll
        for (int j = 1; j < 8; j++) v[j] = cmul(v[j], twl<-1>(g_W512, 8 * j * p));
        __syncthreads();
#pragma unroll
        for (int j = 0; j < 8; j++) sb[(q + 64 * p + 8 * j) * 9 + c] = v[j];
    }
    __syncthreads();
    // stage 2: s=64, p=0 (twiddle-free) -> k1 = r + 64j
#pragma unroll
    for (int j = 0; j < 8; j++) v[j] = sb[(r + 64 * j) * 9 + c];
    fft8<-1>(v);

    float2* out = g_A + (size_t)sig * FFT_N;
#pragma unroll
    for (int j = 0; j < 8; j++) {
        int k1 = r + 64 * j;
        float fr = (float)(n2 * k1) * INV_N;
        fr -= rintf(fr);
        float sn, cs;
        __sincosf(-TWO_PI * fr, &sn, &cs);
        out[(size_t)k1 * N2 + n2] = cmul(v[j], make_float2(cs, sn));
    }
}

// padded smem index: +2 per 16 (keeps float4 alignment, <=2-way banks)
#define PD(i) ((i) + ((((i) >> 4)) << 1))

// ---------------- Pass B: row FFT-1024 (2.8.8.8) x H, iFFT-1024, inv cross twiddle ----------
__global__ void __launch_bounds__(128) passB_main() {
    __shared__ __align__(16) float2 sb[2][1152];
    int row = blockIdx.x;
    int sig = row >> 9, k1 = row & 511;
    const float2* rin  = g_A + (size_t)sig * FFT_N + (size_t)k1 * N2;
    const float2* hrow = g_hS + (size_t)k1 * N2;
    float2*       rout = g_B + (size_t)sig * FFT_N + (size_t)k1 * N2;
    int t = threadIdx.x;
    float2 v[8];

    // ---- forward: stage r2 from gmem registers ----
#pragma unroll
    for (int j = 0; j < 8; j++) v[j] = __ldg(rin + t + 128 * j);
#pragma unroll
    for (int m = 0; m < 4; m++) {
        int p = t + 128 * m;
        float2 e = cadd(v[m], v[m + 4]);
        float2 o = cmul(twl<-1>(g_W1024, p), csub(v[m], v[m + 4]));
        *(float4*)&sb[0][PD(2 * p)] = make_float4(e.x, e.y, o.x, o.y);
    }
    __syncthreads();
    // stage r8, s=2, n=512
#pragma unroll
    for (int j = 0; j < 8; j++) v[j] = sb[0][PD(t + 128 * j)];
    fft8<-1>(v);
    {
        int q = t & 1, p = t >> 1;
#pragma unroll
        for (int j = 1; j < 8; j++) v[j] = cmul(v[j], twl<-1>(g_W1024, 2 * j * p));
#pragma unroll
        for (int j = 0; j < 8; j++) sb[1][PD(q + 16 * p + 2 * j)] = v[j];
    }
    __syncthreads();
    // stage r8, s=16, n=64
#pragma unroll
    for (int j = 0; j < 8; j++) v[j] = sb[1][PD(t + 128 * j)];
    fft8<-1>(v);
    {
        int q = t & 15, p = t >> 4;
#pragma unroll
        for (int j = 1; j < 8; j++) v[j] = cmul(v[j], twl<-1>(g_W1024, 16 * j * p));
#pragma unroll
        for (int j = 0; j < 8; j++) sb[0][PD(q + 128 * p + 16 * j)] = v[j];
    }
    __syncthreads();
    // stage r8, s=128, p=0 -> spectrum X[t+128j] in regs
#pragma unroll
    for (int j = 0; j < 8; j++) v[j] = sb[0][PD(t + 128 * j)];
    fft8<-1>(v);

    // ---- pointwise x H ----
#pragma unroll
    for (int j = 0; j < 8; j++) v[j] = cmul(v[j], __ldg(hrow + t + 128 * j));

    // ---- inverse: stage r2 in regs ----
#pragma unroll
    for (int m = 0; m < 4; m++) {
        int p = t + 128 * m;
        float2 e = cadd(v[m], v[m + 4]);
        float2 o = cmul(twl<1>(g_W1024, p), csub(v[m], v[m + 4]));
        *(float4*)&sb[1][PD(2 * p)] = make_float4(e.x, e.y, o.x, o.y);
    }
    __syncthreads();
#pragma unroll
    for (int j = 0; j < 8; j++) v[j] = sb[1][PD(t + 128 * j)];
    fft8<1>(v);
    {
        int q = t & 1, p = t >> 1;
#pragma unroll
        for (int j = 1; j < 8; j++) v[j] = cmul(v[j], twl<1>(g_W1024, 2 * j * p));
#pragma unroll
        for (int j = 0; j < 8; j++) sb[0][PD(q + 16 * p + 2 * j)] = v[j];
    }
    __syncthreads();
#pragma unroll
    for (int j = 0; j < 8; j++) v[j] = sb[0][PD(t + 128 * j)];
    fft8<1>(v);
    {
        int q = t & 15, p = t >> 4;
#pragma unroll
        for (int j = 1; j < 8; j++) v[j] = cmul(v[j], twl<1>(g_W1024, 16 * j * p));
#pragma unroll
        for (int j = 0; j < 8; j++) sb[1][PD(q + 128 * p + 16 * j)] = v[j];
    }
    __syncthreads();
#pragma unroll
    for (int j = 0; j < 8; j++) v[j] = sb[1][PD(t + 128 * j)];
    fft8<1>(v);

    // ---- inverse cross twiddle + contiguous store ----
#pragma unroll
    for (int j = 0; j < 8; j++) {
        int n2 = t + 128 * j;
        float fr = (float)(n2 * k1) * INV_N;
        fr -= rintf(fr);
        float sn, cs;
        __sincosf(TWO_PI * fr, &sn, &cs);
        rout[n2] = cmul(v[j], make_float2(cs, sn));
    }
}

// ---------------- Pass C: column iFFT-512 (8.8.8) + overlap-save scatter ----------------
__global__ void __launch_bounds__(512, 2) passC(float* __restrict__ dout) {
    __shared__ __align__(16) float2 sb[512 * 9];
    int sig = blockIdx.x >> 7;
    int cb  = (blockIdx.x & 127) << 3;
    int pair = sig / NFRAME;
    int f    = sig - pair * NFRAME;
    const float2* in = g_B + (size_t)sig * FFT_N;

    int c = threadIdx.x & 7, r = threadIdx.x >> 3;
    int n2 = cb + c;
    float2 v[8];
#pragma unroll
    for (int j = 0; j < 8; j++) v[j] = __ldg(in + (size_t)(r + 64 * j) * N2 + n2);
    fft8<1>(v);
#pragma unroll
    for (int j = 1; j < 8; j++) v[j] = cmul(v[j], twl<1>(g_W512, j * r));
#pragma unroll
    for (int j = 0; j < 8; j++) sb[(8 * r + j) * 9 + c] = v[j];
    __syncthreads();
#pragma unroll
    for (int j = 0; j < 8; j++) v[j] = sb[(r + 64 * j) * 9 + c];
    fft8<1>(v);
    {
        int q = r & 7, p = r >> 3;
#pragma unroll
        for (int j = 1; j < 8; j++) v[j] = cmul(v[j], twl<1>(g_W512, 8 * j * p));
        __syncthreads();
#pragma unroll
        for (int j = 0; j < 8; j++) sb[(q + 64 * p + 8 * j) * 9 + c] = v[j];
    }
    __syncthreads();
#pragma unroll
    for (int j = 0; j < 8; j++) v[j] = sb[(r + 64 * j) * 9 + c];
    fft8<1>(v);

    int b0 = 2 * pair;
#pragma unroll
    for (int j = 0; j < 8; j++) {
        int n1 = r + 64 * j;
        int n = n1 * N2 + n2;
        int tt = n - (KLEN - 1);
        if (tt >= 0) {
            long no = (long)f * VALID + tt;
            if (no < LX) {
                dout[(size_t)b0 * LX + no]       = v[j].x;
                dout[((size_t)b0 + 1) * LX + no] = v[j].y;
            }
        }
    }
}

extern "C" void kernel_launch(void* const* d_in, const int* in_sizes, int n_in,
                              void* d_out, int out_size) {
    (void)in_sizes; (void)n_in; (void)out_size;
    const float* x   = (const float*)d_in[0];
    const float* irp = (const float*)d_in[1];
    float* out = (float*)d_out;

    init_luts<<<4, 256>>>();
    passA_H<<<N2 / 8, 512>>>(irp);           // 128 blocks
    passB_H<<<N1, 256>>>();                  // 512 blocks
    passA_main<<<NSIG * (N2 / 8), 512>>>(x); // 3072 blocks
    passB_main<<<NSIG * N1, 128>>>();        // 12288 blocks
    passC<<<NSIG * (N2 / 8), 512>>>(out);    // 3072 blocks
}